// round 1
// baseline (speedup 1.0000x reference)
#include <cuda_runtime.h>

// out[b,c,h,w] = x[b,c,h,w] * (h%3 != 0) * (w%3 != 0)
//
// Derivation: unfold(kh=kw=2, stride=3, dil=2, pad=1) followed by fold with the
// same geometry scatter-adds each extracted patch element back to the position
// it came from. Padded coordinate p is covered by (o,k) iff p = 3o + 2k with
// o in [0,11), k in {0,1}. The sets {3o} and {3o+2} are disjoint, so the
// coverage count is 0 or 1. For the cropped interior coordinate h (p = h+1,
// h in [0,32)), coverage == ((h+1) % 3 != 1) == (h % 3 != 0). Separable in h,w.

__global__ void unfoldfold_mask_kernel(const float4* __restrict__ x,
                                       float4* __restrict__ out,
                                       int n4) {
    int i = blockIdx.x * blockDim.x + threadIdx.x;
    if (i >= n4) return;

    // Each float4 covers 4 consecutive w positions; W=32 floats per row, so a
    // float4 never crosses a row boundary and w0 = (elem index) & 31.
    int e  = i << 2;          // element index of .x
    int w0 = e & 31;
    int h  = (e >> 5) & 31;   // H = 32

    float hm = (h % 3 != 0) ? 1.0f : 0.0f;

    float4 v = x[i];
    v.x *= hm * (float)(((w0 + 0) % 3) != 0);
    v.y *= hm * (float)(((w0 + 1) % 3) != 0);
    v.z *= hm * (float)(((w0 + 2) % 3) != 0);
    v.w *= hm * (float)(((w0 + 3) % 3) != 0);
    out[i] = v;
}

extern "C" void kernel_launch(void* const* d_in, const int* in_sizes, int n_in,
                              void* d_out, int out_size) {
    const float4* x = (const float4*)d_in[0];
    float4* out     = (float4*)d_out;

    int n  = in_sizes[0];      // 64*512*32*32 = 33,554,432
    int n4 = n >> 2;           // 8,388,608 float4s

    const int threads = 256;
    int blocks = (n4 + threads - 1) / threads;
    unfoldfold_mask_kernel<<<blocks, threads>>>(x, out, n4);
}

// round 2
// speedup vs baseline: 1.0559x; 1.0559x over previous
#include <cuda_runtime.h>

// out[b,c,h,w] = x[b,c,h,w] * (h%3 != 0) * (w%3 != 0)
//
// Unfold(k=2, stride=3, dil=2, pad=1) + fold with identical geometry is an
// elementwise coverage mask (coverage count is 0 or 1; separable in h,w).
//
// Traffic optimization: rows with h%3==0 are entirely zero in the output, so
// the input row (exactly one 128B line: W=32 f32) is never loaded — the LDG is
// predicated off, cutting DRAM reads by 11/32.

__global__ void unfoldfold_mask_kernel(const float4* __restrict__ x,
                                       float4* __restrict__ out,
                                       int n4) {
    int i = blockIdx.x * blockDim.x + threadIdx.x;
    if (i >= n4) return;

    // Each float4 covers 4 consecutive w positions; a row is 32 floats =
    // 8 float4s, so a float4 never crosses a row boundary.
    int e  = i << 2;          // element index of .x
    int w0 = e & 31;
    int h  = (e >> 5) & 31;   // H = 32

    float4 v = make_float4(0.f, 0.f, 0.f, 0.f);

    if (h % 3 != 0) {
        v = x[i];             // predicated LDG: masked rows never hit DRAM
        v.x *= (float)(((w0 + 0) % 3) != 0);
        v.y *= (float)(((w0 + 1) % 3) != 0);
        v.z *= (float)(((w0 + 2) % 3) != 0);
        v.w *= (float)(((w0 + 3) % 3) != 0);
    }

    out[i] = v;
}

extern "C" void kernel_launch(void* const* d_in, const int* in_sizes, int n_in,
                              void* d_out, int out_size) {
    const float4* x = (const float4*)d_in[0];
    float4* out     = (float4*)d_out;

    int n  = in_sizes[0];      // 64*512*32*32 = 33,554,432
    int n4 = n >> 2;           // 8,388,608 float4s

    const int threads = 256;
    int blocks = (n4 + threads - 1) / threads;
    unfoldfold_mask_kernel<<<blocks, threads>>>(x, out, n4);
}

// round 3
// speedup vs baseline: 1.1537x; 1.0925x over previous
#include <cuda_runtime.h>

// out[b,c,h,w] = x[b,c,h,w] * (h%3 != 0) * (w%3 != 0)
//
// Unfold(k=2, stride=3, dil=2, pad=1) + fold with identical geometry reduces to
// an elementwise 0/1 coverage mask, separable in h and w.
//
// Traffic: rows with h%3==0 are all-zero in the output, so their input line
// (one 128B row) is never loaded -> reads cut to 21/32. Writes are mandatory
// (d_out is poisoned). Floor = 88 MB read + 134 MB write = 222 MB.
//
// This version: 4 independent float4 loads per thread (MLP_p1=4), each behind
// a single-instruction if so ptxas emits predicated @P LDG.128 (no divergent
// branch region). Chunk stride n4/4 is a multiple of 256 float4 (whole 32x32
// planes), so all 4 accesses of a thread share the same (h,w) mask.

__global__ void unfoldfold_mask_kernel(const float4* __restrict__ x,
                                       float4* __restrict__ out,
                                       int q) {
    int i = blockIdx.x * blockDim.x + threadIdx.x;
    if (i >= q) return;

    int e  = i << 2;           // element index of .x within the plane stream
    int w0 = e & 31;           // W = 32 floats per row; float4 never crosses rows
    int h  = (e >> 5) & 31;    // H = 32

    float hm = (h % 3 != 0) ? 1.0f : 0.0f;
    float m0 = hm * (float)(((w0 + 0) % 3) != 0);
    float m1 = hm * (float)(((w0 + 1) % 3) != 0);
    float m2 = hm * (float)(((w0 + 2) % 3) != 0);
    float m3 = hm * (float)(((w0 + 3) % 3) != 0);

    bool ld = (h % 3 != 0);

    float4 v0 = make_float4(0.f, 0.f, 0.f, 0.f);
    float4 v1 = v0, v2 = v0, v3 = v0;

    // Single-load bodies -> predicated LDG.128, issued back-to-back (MLP=4).
    if (ld) v0 = x[i];
    if (ld) v1 = x[i + q];
    if (ld) v2 = x[i + 2 * q];
    if (ld) v3 = x[i + 3 * q];

    v0.x *= m0; v0.y *= m1; v0.z *= m2; v0.w *= m3;
    v1.x *= m0; v1.y *= m1; v1.z *= m2; v1.w *= m3;
    v2.x *= m0; v2.y *= m1; v2.z *= m2; v2.w *= m3;
    v3.x *= m0; v3.y *= m1; v3.z *= m2; v3.w *= m3;

    out[i]         = v0;
    out[i + q]     = v1;
    out[i + 2 * q] = v2;
    out[i + 3 * q] = v3;
}

extern "C" void kernel_launch(void* const* d_in, const int* in_sizes, int n_in,
                              void* d_out, int out_size) {
    const float4* x = (const float4*)d_in[0];
    float4* out     = (float4*)d_out;

    int n  = in_sizes[0];      // 64*512*32*32 = 33,554,432
    int n4 = n >> 2;           // 8,388,608 float4s
    int q  = n4 >> 2;          // 2,097,152 float4s per chunk (plane-aligned)

    const int threads = 256;
    int blocks = (q + threads - 1) / threads;   // 8192 blocks
    unfoldfold_mask_kernel<<<blocks, threads>>>(x, out, q);
}